// round 3
// baseline (speedup 1.0000x reference)
#include <cuda_runtime.h>
#include <cuda_bf16.h>
#include <cstdint>

#define NS 7
#define NR 6
#define SR 42          // NS * NR
#define TPB 128
#define ROWF 44        // padded shared row stride (floats), even for float2 alignment

// sqrt((2l+1)/(4*pi)) for l = 0..6
__device__ __constant__ float kCoef[7] = {
    0.28209479177387814f,
    0.48860251190291992f,
    0.63078313050504009f,
    0.74635266518023078f,
    0.84628437532163443f,
    0.93560257962738882f,
    1.01710723628205458f
};

__global__ void __launch_bounds__(TPB)
dime_sbf_kernel(const float* __restrict__ o,
                const float* __restrict__ rbf,
                const void*  __restrict__ src_v,
                const void*  __restrict__ dst_v,
                float* __restrict__ out,
                long long E, long long T)
{
    __shared__ float cbf_ex[TPB * ROWF];   // expanded coefficients, one 42-wide row/triplet
    __shared__ int   src_sh[TPB];          // E = 1e6 fits in int32

    const int tid = threadIdx.x;
    const long long base = (long long)blockIdx.x * TPB;
    const long long t = base + tid;

    // ---- index dtype detection (int64 requested, JAX may demote to int32) ----
    const long long* s64 = (const long long*)src_v;
    const int*       s32 = (const int*)src_v;
    const long long* d64 = (const long long*)dst_v;
    const int*       d32 = (const int*)dst_v;
    bool is64 = true;
    #pragma unroll
    for (int k = 0; k < 4; k++) {
        long long v = __ldg(&s64[k]);
        if (v < 0 || v >= E) is64 = false;
    }

    // ---- phase 1: per-triplet spherical basis, expanded into shared ----
    if (t < T) {
        long long si, di;
        if (is64) { si = __ldcs(&s64[t]); di = __ldcs(&d64[t]); }
        else      { si = (long long)__ldcs(&s32[t]); di = (long long)__ldcs(&d32[t]); }

        const float* p1 = o + si * 3;
        const float* p2 = o + di * 3;
        float ax = __ldg(p1 + 0), ay = __ldg(p1 + 1), az = __ldg(p1 + 2);
        float bx = __ldg(p2 + 0), by = __ldg(p2 + 1), bz = __ldg(p2 + 2);

        float dot = ax*bx + ay*by + az*bz;
        float n1  = ax*ax + ay*ay + az*az;
        float n2  = bx*bx + by*by + bz*bz;
        // cos(atan2(||cross||, dot)) == dot / (|R1||R2|)
        float c = dot * rsqrtf(n1 * n2);

        float P[NS];
        P[0] = 1.0f;
        P[1] = c;
        #pragma unroll
        for (int l = 2; l < NS; l++) {
            P[l] = ((float)(2*l - 1) * c * P[l-1] - (float)(l - 1) * P[l-2])
                   * (1.0f / (float)l);
        }
        float2* rowp = (float2*)(cbf_ex + tid * ROWF);
        #pragma unroll
        for (int s = 0; s < NS; s++) {
            float cv = kCoef[s] * P[s];
            float2 q = make_float2(cv, cv);
            rowp[3*s + 0] = q;   // each s-block is 6 floats = 3 float2, starts at even j
            rowp[3*s + 1] = q;
            rowp[3*s + 2] = q;
        }
        src_sh[tid] = (int)si;
    }
    __syncthreads();

    // ---- phase 2: cooperative coalesced emission of the 128x42 tile ----
    float* out_blk = out + base * SR;
    const long long rem = T - base;

    if (rem >= TPB) {
        // full tile: quads of flat index e = 4*i4; j = e mod 42 is ALWAYS even
        int e  = tid * 4;
        int tl = e / SR;              // compiler mul-shift (once)
        int j  = e - tl * SR;
        const int n4 = TPB * SR / 4;  // 1344
        #pragma unroll 4
        for (int i4 = tid; i4 < n4; i4 += TPB) {
            const float* rowA = rbf + (long long)src_sh[tl] * SR;
            float2 a, b, ca, cb;
            if (j <= 38) {
                a  = __ldg((const float2*)(rowA + j));
                b  = __ldg((const float2*)(rowA + j + 2));
                const float2* cp = (const float2*)(cbf_ex + tl * ROWF + j);
                ca = cp[0];
                cb = cp[1];
            } else {  // j == 40: quad straddles rows (40,41 | 0,1 of tl+1)
                a  = __ldg((const float2*)(rowA + 40));
                const float* rowB = rbf + (long long)src_sh[tl + 1] * SR;
                b  = __ldg((const float2*)rowB);
                ca = *(const float2*)(cbf_ex + tl * ROWF + 40);
                cb = *(const float2*)(cbf_ex + (tl + 1) * ROWF);
            }
            float4 v = make_float4(a.x * ca.x, a.y * ca.y, b.x * cb.x, b.y * cb.y);
            __stcs((float4*)out_blk + i4, v);

            // advance flat index by 512 = 12*42 + 8
            tl += 12;
            j  += 8;
            if (j >= SR) { j -= SR; tl += 1; }
        }
    } else {
        // tail block: scalar with bounds
        int ne = (int)rem * SR;
        for (int e = tid; e < ne; e += TPB) {
            int tl = e / SR;
            int j  = e - tl * SR;
            float r = __ldg(&rbf[(long long)src_sh[tl] * SR + j]);
            out_blk[e] = r * cbf_ex[tl * ROWF + j];
        }
    }
}

extern "C" void kernel_launch(void* const* d_in, const int* in_sizes, int n_in,
                              void* d_out, int out_size)
{
    const float* o   = (const float*)d_in[0];    // [E, 3]
    const float* rbf = (const float*)d_in[1];    // [E, 42]
    const void*  src = d_in[2];                  // [T] int64 (or demoted int32)
    const void*  dst = d_in[3];                  // [T]
    float* out = (float*)d_out;                  // [T, 42]

    const long long E = (long long)in_sizes[0] / 3;
    const long long T = (long long)in_sizes[2];

    const int blocks = (int)((T + TPB - 1) / TPB);
    dime_sbf_kernel<<<blocks, TPB>>>(o, rbf, src, dst, out, E, T);
}